// round 6
// baseline (speedup 1.0000x reference)
#include <cuda_runtime.h>
#include <math.h>

// ---------------------------------------------------------------------------
// NISQ classifier via Pauli-transfer-matrix simulation, quad-ownership passes.
// State c[p], p = 10 base-4 digits (slots). Qubit -> slot:
//   q:    0  1  2  3  4  5  6  7  8  9
//   slot: 0  2  3  4  5  1  6  7  8  9
// Tile A (KIND 0): slots 0-5 (bits 0-11)          -> CNOT 01,12,23,34,45
// Tile B (KIND 1): slots {0,1,6..9} (bits 0-3,12-19) -> CNOT 56,67,78,89,90
// Each thread owns ONE row (dc) of a 16-elem (2-digit) group; partner row
// (3-dc) fetched via shfl_xor(3). 512 threads/block, 2 groups/thread.
// ---------------------------------------------------------------------------

#define NSTATE (1 << 20)
__device__ float g_c[NSTATE];   // PTM state vector (4 MB)

// Linear bank swizzle: phys = u ^ SWc(u). Verified injective (conflict-free)
// for all pass lane-patterns (0,2)(2,3)(3,4)(4,5)(5,1)(1,2)(5,0) and the
// float4 boundary pattern.
__device__ __host__ constexpr unsigned SWc(unsigned u) {
    return ((((u >> 5) ^ (u >> 10)) & 1u))
         | ((((u >> 6) ^ (u >> 7) ^ (u >> 11)) & 1u) << 1)
         | ((((u >> 6) ^ (u >> 10)) & 1u) << 2)
         | ((((u >> 5) ^ (u >> 7) ^ (u >> 8) ^ (u >> 11)) & 1u) << 3)
         | ((((u >> 6) ^ (u >> 9)) & 1u) << 4);
}

// Build fused single-qubit PTM op: M = phase*amp*depol1*Rot (4x4, row I = e0)
__device__ __forceinline__ void build_M(float phi, float th, float om, float* M) {
    float cphi = cosf(phi), sphi = sinf(phi);
    float cth  = cosf(th),  sth  = sinf(th);
    float com  = cosf(om),  som  = sinf(om);
    float A[9]  = {com, -som, 0.f,  som, com, 0.f,  0.f, 0.f, 1.f};
    float Bm[9] = {cth, 0.f, sth,   0.f, 1.f, 0.f,  -sth, 0.f, cth};
    float C[9]  = {cphi, -sphi, 0.f, sphi, cphi, 0.f, 0.f, 0.f, 1.f};
    float AB[9], R[9];
#pragma unroll
    for (int i = 0; i < 3; i++)
#pragma unroll
        for (int j = 0; j < 3; j++) {
            float s = 0.f;
#pragma unroll
            for (int k = 0; k < 3; k++) s += A[i*3+k] * Bm[k*3+j];
            AB[i*3+j] = s;
        }
#pragma unroll
    for (int i = 0; i < 3; i++)
#pragma unroll
        for (int j = 0; j < 3; j++) {
            float s = 0.f;
#pragma unroll
            for (int k = 0; k < 3; k++) s += AB[i*3+k] * C[k*3+j];
            R[i*3+j] = s;
        }
    const float gamma = -expm1f(-1e-7f / 0.05f);
    const float gph   = -expm1f(-1e-7f / 0.07f);
    const float c1    = 1.0f - 4.0f * 0.001f / 3.0f;
    float sq = sqrtf((1.f - gamma) * (1.f - gph));
    float a1 = sq * c1, z1 = (1.f - gamma) * c1, g1 = gamma;
    M[0]  = 1.f; M[1]  = 0.f;       M[2]  = 0.f;       M[3]  = 0.f;
    M[4]  = 0.f; M[5]  = a1 * R[0]; M[6]  = a1 * R[1]; M[7]  = a1 * R[2];
    M[8]  = 0.f; M[9]  = a1 * R[3]; M[10] = a1 * R[4]; M[11] = a1 * R[5];
    M[12] = g1;  M[13] = z1 * R[6]; M[14] = z1 * R[7]; M[15] = z1 * R[8];
}

// Quad pass: thread owns row dc of 2 groups. Derivation (i = 4*dc + dt,
// perm tbl {0,1,14,15, 5,4,11,10, 9,8,7,6, 12,13,2,3}, signs on i=7,10):
//   dc=0: u = {o0,o1,p2,p3}          (p = row 3)
//   dc=1: u = {o1,o0,p3,-p2}         (p = row 2)
//   dc=2: u = {o1,o0,-p3,p2}         (p = row 1)
//   dc=3: u = {o0,o1,p2,p3}          (p = row 0)
// control noise: row0: u; rows1,2: aN*u; row3: gN*{p0,p1,o2,o3} + zN*u
// target noise (per row): {a0, aN a1, aN a2, gN a0 + zN a3}
template<int PC, int PT, bool HASMT>
__device__ __forceinline__ void quadpass(float* __restrict__ t,
                                         const float* __restrict__ MT,
                                         float aN, float zN, float gN) {
    constexpr int sc = 2 * PC, st = 2 * PT;
    constexpr int plo  = (sc < st) ? sc : st;
    constexpr int phi_ = (sc < st) ? st : sc;
    constexpr int midw = phi_ - plo - 2;
    constexpr unsigned C1 = (1u << st) ^ SWc(1u << st);
    constexpr unsigned C2 = (2u << st) ^ SWc(2u << st);
    constexpr unsigned C3 = (3u << st) ^ SWc(3u << st);

    unsigned tid = threadIdx.x;
    unsigned dc  = tid & 3u;
    bool  swp  = (dc == 1u) || (dc == 2u);
    bool  r3   = (dc == 3u);
    float sg   = (dc == 1u) ? 1.f : -1.f;
    float mult = swp ? aN : 1.f;

    float m5=0,m6=0,m7=0,m9=0,m10=0,m11=0,m12=0,m13=0,m14=0,m15=0;
    if (HASMT) {
        m5 = MT[5];  m6 = MT[6];  m7 = MT[7];
        m9 = MT[9];  m10 = MT[10]; m11 = MT[11];
        m12 = MT[12]; m13 = MT[13]; m14 = MT[14]; m15 = MT[15];
    }

#pragma unroll
    for (int half = 0; half < 2; half++) {
        unsigned G    = (tid >> 2) + (unsigned)half * 128u;
        unsigned lo   = G & ((1u << plo) - 1u);
        unsigned rest = G >> plo;
        unsigned mid  = rest & ((1u << midw) - 1u);
        unsigned hi   = rest >> midw;
        unsigned base = lo | (mid << (plo + 2)) | (hi << (phi_ + 2)) | (dc << sc);
        unsigned pb   = base ^ SWc(base);

        float o0 = t[pb];
        float o1 = t[pb ^ C1];
        float o2 = t[pb ^ C2];
        float o3 = t[pb ^ C3];
        if (HASMT) {
            float x1 = m5  * o1 + m6  * o2 + m7  * o3;
            float x2 = m9  * o1 + m10 * o2 + m11 * o3;
            float x3 = m12 * o0 + m13 * o1 + m14 * o2 + m15 * o3;
            o1 = x1; o2 = x2; o3 = x3;
        }
        float p0 = __shfl_xor_sync(0xFFFFFFFFu, o0, 3);
        float p1 = __shfl_xor_sync(0xFFFFFFFFu, o1, 3);
        float p2 = __shfl_xor_sync(0xFFFFFFFFu, o2, 3);
        float p3 = __shfl_xor_sync(0xFFFFFFFFu, o3, 3);

        float a0 = swp ? o1 : o0;
        float a1 = swp ? o0 : o1;
        float a2 = swp ? sg * p3 : p2;
        float a3 = swp ? (-sg) * p2 : p3;

        float out0 = r3 ? (gN * p0 + zN * a0) : mult * a0;
        float out1 = r3 ? (gN * p1 + zN * a1) : mult * a1;
        float out2 = r3 ? (gN * o2 + zN * a2) : mult * a2;
        float out3 = r3 ? (gN * o3 + zN * a3) : mult * a3;

        t[pb]      = out0;
        t[pb ^ C1] = aN * out1;
        t[pb ^ C2] = aN * out2;
        t[pb ^ C3] = gN * out0 + zN * out3;
    }
}

// ---------------------------------------------------------------------------
// Sim kernel: 256 blocks x 512 threads, 4096-float swizzled smem tile.
// KIND0 folds M0 (q0 = digit bits 0-1 = one float4) into the boundary load.
// ---------------------------------------------------------------------------
template<int KIND, bool INIT>
__global__ __launch_bounds__(512) void sim_kernel(const float* __restrict__ wts,
                                                  int layer) {
    __shared__ float t[4096];
    __shared__ float sM[10][16];
    unsigned blk = blockIdx.x, tid = threadIdx.x;

    if (tid < 10) {
        int q = (int)tid;
        const float* a = wts + (layer * 10 + q) * 3;
        build_M(a[0], a[1], a[2], sM[q]);
    }
    __syncthreads();

    auto gidx = [&](unsigned u) -> unsigned {
        if (KIND == 0) return u | (blk << 12);
        else           return (u & 15u) | (blk << 4) | ((u >> 4) << 12);
    };

    // boundary load (+ fold M0 for KIND 0: each float4 is one digit-0 quad)
    float M05=sM[0][5],  M06=sM[0][6],  M07=sM[0][7];
    float M09=sM[0][9],  M010=sM[0][10], M011=sM[0][11];
    float M012=sM[0][12],M013=sM[0][13],M014=sM[0][14],M015=sM[0][15];
#pragma unroll
    for (int k = 0; k < 2; k++) {
        unsigned u = tid * 8u + (unsigned)k * 4u;
        float4 r;
        if (INIT) {
            unsigned p = gidx(u);
            float v = ((((p >> 1) ^ p) & 0x55555u) == 0u) ? 1.0f : 0.0f;
            r.x = v; r.y = 0.f; r.z = 0.f; r.w = v;
        } else {
            r = *(const float4*)&g_c[gidx(u)];
        }
        if (KIND == 0) {
            float x1 = M05  * r.y + M06  * r.z + M07  * r.w;
            float x2 = M09  * r.y + M010 * r.z + M011 * r.w;
            float x3 = M012 * r.x + M013 * r.y + M014 * r.z + M015 * r.w;
            r.y = x1; r.z = x2; r.w = x3;
        }
        unsigned sw = SWc(u);
        t[(u + 0) ^ sw] = r.x;
        t[(u + 1) ^ sw] = r.y;
        t[(u + 2) ^ sw] = r.z;
        t[(u + 3) ^ sw] = r.w;
    }
    __syncthreads();

    const float gamma = -expm1f(-1e-7f / 0.05f);
    const float gph   = -expm1f(-1e-7f / 0.07f);
    const float c2    = 1.0f - 4.0f * 0.01f / 3.0f;
    const float aN = sqrtf((1.f - gamma) * (1.f - gph)) * c2;
    const float zN = (1.f - gamma) * c2;
    const float gN = gamma;

    if (KIND == 0) {
        // local pos: q0->0 q5->1 q1->2 q2->3 q3->4 q4->5
        quadpass<0, 2, true>(t, sM[1], aN, zN, gN); __syncthreads(); // M1, CNOT(q0,q1)
        quadpass<2, 3, true>(t, sM[2], aN, zN, gN); __syncthreads(); // M2, CNOT(q1,q2)
        quadpass<3, 4, true>(t, sM[3], aN, zN, gN); __syncthreads(); // M3, CNOT(q2,q3)
        quadpass<4, 5, true>(t, sM[4], aN, zN, gN); __syncthreads(); // M4, CNOT(q3,q4)
        quadpass<5, 1, true>(t, sM[5], aN, zN, gN); __syncthreads(); // M5, CNOT(q4,q5)
    } else {
        // local pos: q0->0 q5->1 q6->2 q7->3 q8->4 q9->5
        quadpass<1, 2, true >(t, sM[6], aN, zN, gN); __syncthreads(); // M6, CNOT(q5,q6)
        quadpass<2, 3, true >(t, sM[7], aN, zN, gN); __syncthreads(); // M7, CNOT(q6,q7)
        quadpass<3, 4, true >(t, sM[8], aN, zN, gN); __syncthreads(); // M8, CNOT(q7,q8)
        quadpass<4, 5, true >(t, sM[9], aN, zN, gN); __syncthreads(); // M9, CNOT(q8,q9)
        quadpass<5, 0, false>(t, 0,     aN, zN, gN); __syncthreads(); // CNOT(q9,q0)
    }

#pragma unroll
    for (int k = 0; k < 2; k++) {
        unsigned u = tid * 8u + (unsigned)k * 4u;
        unsigned sw = SWc(u);
        float4 r;
        r.x = t[(u + 0) ^ sw];
        r.y = t[(u + 1) ^ sw];
        r.z = t[(u + 2) ^ sw];
        r.w = t[(u + 3) ^ sw];
        *(float4*)&g_c[gidx(u)] = r;
    }
}

// ---------------------------------------------------------------------------
// Logits: one block per batch row.
// ---------------------------------------------------------------------------
__global__ __launch_bounds__(256) void logits_kernel(
    const float* __restrict__ x, const float* __restrict__ bvec,
    const float* __restrict__ w, float* __restrict__ out) {
    __shared__ float xs[1024];
    __shared__ float cA[10], cB[10];
    __shared__ float red[8];
    int row = blockIdx.x, tid = threadIdx.x;

    for (int m = tid; m < 1024; m += 256)
        xs[m] = x[row * 1024 + m] + bvec[m];

    if (tid < 10) {
        const int slot_of_q[10] = {0, 2, 3, 4, 5, 1, 6, 7, 8, 9};
        int q = tid;
        int j = 9 - q;
        int s2 = 2 * slot_of_q[q];
        cA[j] = w[2 * q] * g_c[1u << s2];
        cB[j] = w[2 * q + 1] * 0.96f * g_c[3u << s2];   // readout: 1-2*0.02
    }
    __syncthreads();

    float acc = 0.f;
    for (int m = tid; m < 1024; m += 256) {
        float xm = xs[m];
        float s = 0.f;
#pragma unroll
        for (int j = 0; j < 10; j++) {
            s += cA[j] * xs[m ^ (1 << j)];
            s += cB[j] * (((m >> j) & 1) ? -xm : xm);
        }
        acc += xm * s;
    }
#pragma unroll
    for (int off = 16; off > 0; off >>= 1)
        acc += __shfl_down_sync(0xFFFFFFFFu, acc, off);
    if ((tid & 31) == 0) red[tid >> 5] = acc;
    __syncthreads();
    if (tid < 8) {
        float a = red[tid];
#pragma unroll
        for (int off = 4; off > 0; off >>= 1)
            a += __shfl_down_sync(0xFFu, a, off);
        if (tid == 0) out[row] = 1.f / (1.f + expf(-a));
    }
}

// ---------------------------------------------------------------------------
extern "C" void kernel_launch(void* const* d_in, const int* in_sizes, int n_in,
                              void* d_out, int out_size) {
    const float* x = nullptr;
    const float* bv = nullptr;
    const float* w = nullptr;
    const float* cw = nullptr;
    for (int i = 0; i < n_in; i++) {
        switch (in_sizes[i]) {
            case 2048 * 1024: x = (const float*)d_in[i]; break;
            case 1024:        bv = (const float*)d_in[i]; break;
            case 20:          w = (const float*)d_in[i]; break;
            case 90:          cw = (const float*)d_in[i]; break;
            default: break;  // P_tensor unused
        }
    }

    sim_kernel<0, true ><<<256, 512>>>(cw, 0);
    sim_kernel<1, false><<<256, 512>>>(cw, 0);
    sim_kernel<0, false><<<256, 512>>>(cw, 1);
    sim_kernel<1, false><<<256, 512>>>(cw, 1);
    sim_kernel<0, false><<<256, 512>>>(cw, 2);
    sim_kernel<1, false><<<256, 512>>>(cw, 2);
    logits_kernel<<<2048, 256>>>(x, bv, w, (float*)d_out);
}